// round 1
// baseline (speedup 1.0000x reference)
#include <cuda_runtime.h>

// Problem constants
#define Bb  8
#define Ssq 1024
#define Hh  16
#define Dd  64
#define Ww  1024   // hidden = H*D

// Scratch for Q/K/V in [B,H,S,D] layout (module-load allocated, not runtime alloc)
__device__ float g_q[Bb * Hh * Ssq * Dd];
__device__ float g_k[Bb * Hh * Ssq * Dd];
__device__ float g_v[Bb * Hh * Ssq * Dd];

// ---------------------------------------------------------------------------
// Fused QKV projection GEMM: C[8192,1024] = A[8192,1024] @ W[1024,1024] + b
// blockIdx.z selects which of Q/K/V. Output scattered to [B,H,S,D] scratch.
// 128x128x16 tile, 256 threads, 8x8 per-thread (two 64-split quadrants).
// ---------------------------------------------------------------------------
__global__ __launch_bounds__(256) void qkv_gemm(
    const float* __restrict__ from_t, const float* __restrict__ to_t,
    const float* __restrict__ Wq, const float* __restrict__ bq,
    const float* __restrict__ Wk, const float* __restrict__ bk,
    const float* __restrict__ Wv, const float* __restrict__ bv)
{
    const int which = blockIdx.z;
    const float* A  = (which == 0) ? from_t : to_t;
    const float* Wm = (which == 0) ? Wq : (which == 1) ? Wk : Wv;
    const float* bb = (which == 0) ? bq : (which == 1) ? bk : bv;
    float* outp     = (which == 0) ? g_q : (which == 1) ? g_k : g_v;

    __shared__ float Asm[16][128];   // A transposed: [k][m]
    __shared__ float Bsm[16][128];   // W natural:    [k][n]

    const int tid = threadIdx.x;
    const int m0 = blockIdx.y * 128;
    const int n0 = blockIdx.x * 128;

    // global->smem load indices
    const int a_r = tid >> 2;          // 0..63
    const int a_c = (tid & 3) << 2;    // 0,4,8,12
    const int b_r = tid >> 5;          // 0..7
    const int b_c = (tid & 31) << 2;   // 0..124

    const int ty = tid >> 4;           // 0..15
    const int tx = tid & 15;           // 0..15

    float acc[8][8];
#pragma unroll
    for (int i = 0; i < 8; i++)
#pragma unroll
        for (int j = 0; j < 8; j++) acc[i][j] = 0.f;

    for (int k0 = 0; k0 < Ww; k0 += 16) {
        float4 av0 = *(const float4*)(A + (m0 + a_r) * Ww + k0 + a_c);
        float4 av1 = *(const float4*)(A + (m0 + a_r + 64) * Ww + k0 + a_c);
        float4 bv0 = *(const float4*)(Wm + (k0 + b_r) * Ww + n0 + b_c);
        float4 bv1 = *(const float4*)(Wm + (k0 + b_r + 8) * Ww + n0 + b_c);
        __syncthreads();   // previous tile's compute done before overwrite
        Asm[a_c + 0][a_r] = av0.x;
        Asm[a_c + 1][a_r] = av0.y;
        Asm[a_c + 2][a_r] = av0.z;
        Asm[a_c + 3][a_r] = av0.w;
        Asm[a_c + 0][a_r + 64] = av1.x;
        Asm[a_c + 1][a_r + 64] = av1.y;
        Asm[a_c + 2][a_r + 64] = av1.z;
        Asm[a_c + 3][a_r + 64] = av1.w;
        *(float4*)&Bsm[b_r][b_c]     = bv0;
        *(float4*)&Bsm[b_r + 8][b_c] = bv1;
        __syncthreads();
#pragma unroll
        for (int kk = 0; kk < 16; kk++) {
            float a[8], b[8];
            *(float4*)&a[0] = *(const float4*)&Asm[kk][ty * 4];
            *(float4*)&a[4] = *(const float4*)&Asm[kk][64 + ty * 4];
            *(float4*)&b[0] = *(const float4*)&Bsm[kk][tx * 4];
            *(float4*)&b[4] = *(const float4*)&Bsm[kk][64 + tx * 4];
#pragma unroll
            for (int i = 0; i < 8; i++)
#pragma unroll
                for (int j = 0; j < 8; j++)
                    acc[i][j] = fmaf(a[i], b[j], acc[i][j]);
        }
    }

    // epilogue: + bias, scatter to [B,H,S,D]
    float biasv[8];
    *(float4*)&biasv[0] = *(const float4*)(bb + n0 + tx * 4);
    *(float4*)&biasv[4] = *(const float4*)(bb + n0 + 64 + tx * 4);

#pragma unroll
    for (int i = 0; i < 8; i++) {
        const int m = m0 + ((i < 4) ? (ty * 4 + i) : (64 + ty * 4 + (i - 4)));
        const int bidx = m >> 10;      // m / S
        const int s    = m & 1023;     // m % S
#pragma unroll
        for (int jq = 0; jq < 2; jq++) {
            const int n = n0 + jq * 64 + tx * 4;
            const int h = n >> 6;      // n / D
            const int d = n & 63;      // n % D
            float4 v;
            v.x = acc[i][jq * 4 + 0] + biasv[jq * 4 + 0];
            v.y = acc[i][jq * 4 + 1] + biasv[jq * 4 + 1];
            v.z = acc[i][jq * 4 + 2] + biasv[jq * 4 + 2];
            v.w = acc[i][jq * 4 + 3] + biasv[jq * 4 + 3];
            *(float4*)(outp + ((bidx * Hh + h) * Ssq + s) * Dd + d) = v;
        }
    }
}

// ---------------------------------------------------------------------------
// Flash attention, fp32. One block = (b,h) x 64 query rows. 16 key tiles of 64.
// Q/K in smem d-major with XOR swizzle; V row-major swizzled; online softmax.
// ---------------------------------------------------------------------------
__device__ __forceinline__ int swz(int k, int r) {
    return k * 64 + (r ^ (((k >> 2) & 15) << 2));
}

__global__ __launch_bounds__(256) void attn_kernel(float* __restrict__ out)
{
    extern __shared__ float sm[];
    float* Qs = sm;                 // 4096: [d][r] swizzled, pre-scaled by 1/8
    float* Ks = sm + 4096;          // 4096: [d][c] swizzled
    float* Vs = sm + 8192;          // 4096: [k][d] swizzled
    float* Ps = sm + 12288;         // 64 x 68 (scores -> probs)
    float* smm = Ps + 64 * 68;      // running max, 64
    float* sml = smm + 64;          // running sum, 64
    float* smc = sml + 64;          // per-iter correction, 64

    const int tid = threadIdx.x;
    const int bh = blockIdx.y;                 // 0..127 (b*16+h)
    const int q0 = blockIdx.x * 64;

    const float* Qg = g_q + (bh * Ssq + q0) * Dd;
    const float* Kg = g_k + bh * Ssq * Dd;
    const float* Vg = g_v + bh * Ssq * Dd;

    // load Q (scaled, transposed to d-major, swizzled)
#pragma unroll
    for (int i = 0; i < 4; i++) {
        int c = i * 256 + tid;          // float4 index 0..1023
        int r = c >> 4;                 // row 0..63
        int d4 = (c & 15) << 2;         // d 0..60
        float4 v = *(const float4*)(Qg + r * 64 + d4);
        Qs[swz(d4 + 0, r)] = v.x * 0.125f;
        Qs[swz(d4 + 1, r)] = v.y * 0.125f;
        Qs[swz(d4 + 2, r)] = v.z * 0.125f;
        Qs[swz(d4 + 3, r)] = v.w * 0.125f;
    }
    if (tid < 64) { smm[tid] = -1e30f; sml[tid] = 0.f; }

    const int ty = tid >> 4, tx = tid & 15;
    const int r0 = ty * 4, c0 = tx * 4;

    float O[4][4];
#pragma unroll
    for (int i = 0; i < 4; i++)
#pragma unroll
        for (int j = 0; j < 4; j++) O[i][j] = 0.f;

    for (int kt = 0; kt < 16; kt++) {
        const float* Kt = Kg + kt * 64 * 64;
        const float* Vt = Vg + kt * 64 * 64;
        __syncthreads();   // previous phase C done (and Q stores on iter 0)

        // load K (transposed+swizzled) and V (row-major, swizzled)
#pragma unroll
        for (int i = 0; i < 4; i++) {
            int c = i * 256 + tid;
            int r = c >> 4;
            int d4 = (c & 15) << 2;
            float4 kv = *(const float4*)(Kt + r * 64 + d4);
            Ks[swz(d4 + 0, r)] = kv.x;
            Ks[swz(d4 + 1, r)] = kv.y;
            Ks[swz(d4 + 2, r)] = kv.z;
            Ks[swz(d4 + 3, r)] = kv.w;
            float4 vv = *(const float4*)(Vt + r * 64 + d4);
            *(float4*)&Vs[r * 64 + (d4 ^ (((r >> 2) & 15) << 2))] = vv;
        }
        __syncthreads();

        // phase A: S = (Q/8) K^T  -> Ps
        float acc[4][4];
#pragma unroll
        for (int i = 0; i < 4; i++)
#pragma unroll
            for (int j = 0; j < 4; j++) acc[i][j] = 0.f;
#pragma unroll 8
        for (int kk = 0; kk < 64; kk++) {
            const int cs = ((kk >> 2) & 15) << 2;
            float4 q = *(const float4*)&Qs[kk * 64 + (r0 ^ cs)];
            float4 k = *(const float4*)&Ks[kk * 64 + (c0 ^ cs)];
            float qa[4] = {q.x, q.y, q.z, q.w};
            float ka[4] = {k.x, k.y, k.z, k.w};
#pragma unroll
            for (int i = 0; i < 4; i++)
#pragma unroll
                for (int j = 0; j < 4; j++)
                    acc[i][j] = fmaf(qa[i], ka[j], acc[i][j]);
        }
#pragma unroll
        for (int i = 0; i < 4; i++) {
            float4 v = make_float4(acc[i][0], acc[i][1], acc[i][2], acc[i][3]);
            *(float4*)&Ps[(r0 + i) * 68 + c0] = v;
        }
        __syncthreads();

        // phase B: online softmax (4 threads per row)
        {
            const int row = tid >> 2, jj = tid & 3;
            const float m_old = smm[row];
            float pv[16];
            float lm = -1e30f;
#pragma unroll
            for (int e = 0; e < 16; e++) {
                pv[e] = Ps[row * 68 + jj * 16 + e];
                lm = fmaxf(lm, pv[e]);
            }
            lm = fmaxf(lm, __shfl_xor_sync(0xffffffffu, lm, 1));
            lm = fmaxf(lm, __shfl_xor_sync(0xffffffffu, lm, 2));
            const float mnew = fmaxf(m_old, lm);
            float lsum = 0.f;
#pragma unroll
            for (int e = 0; e < 16; e++) {
                float p = __expf(pv[e] - mnew);
                lsum += p;
                Ps[row * 68 + jj * 16 + e] = p;
            }
            lsum += __shfl_xor_sync(0xffffffffu, lsum, 1);
            lsum += __shfl_xor_sync(0xffffffffu, lsum, 2);
            if (jj == 0) {
                smc[row] = __expf(m_old - mnew);
                sml[row] = sml[row] * smc[row] + lsum;
                smm[row] = mnew;
            }
        }
        __syncthreads();

        // phase C: O = O*corr + P @ V
#pragma unroll
        for (int i = 0; i < 4; i++) {
            const float cr = smc[r0 + i];
#pragma unroll
            for (int j = 0; j < 4; j++) O[i][j] *= cr;
        }
#pragma unroll 2
        for (int kk = 0; kk < 64; kk += 4) {
            const int cs = ((kk >> 2) & 15) << 2;
            float4 v0 = *(const float4*)&Vs[(kk + 0) * 64 + (c0 ^ cs)];
            float4 v1 = *(const float4*)&Vs[(kk + 1) * 64 + (c0 ^ cs)];
            float4 v2 = *(const float4*)&Vs[(kk + 2) * 64 + (c0 ^ cs)];
            float4 v3 = *(const float4*)&Vs[(kk + 3) * 64 + (c0 ^ cs)];
#pragma unroll
            for (int i = 0; i < 4; i++) {
                float4 p = *(const float4*)&Ps[(r0 + i) * 68 + kk];
                O[i][0] = fmaf(p.x, v0.x, O[i][0]);
                O[i][1] = fmaf(p.x, v0.y, O[i][1]);
                O[i][2] = fmaf(p.x, v0.z, O[i][2]);
                O[i][3] = fmaf(p.x, v0.w, O[i][3]);
                O[i][0] = fmaf(p.y, v1.x, O[i][0]);
                O[i][1] = fmaf(p.y, v1.y, O[i][1]);
                O[i][2] = fmaf(p.y, v1.z, O[i][2]);
                O[i][3] = fmaf(p.y, v1.w, O[i][3]);
                O[i][0] = fmaf(p.z, v2.x, O[i][0]);
                O[i][1] = fmaf(p.z, v2.y, O[i][1]);
                O[i][2] = fmaf(p.z, v2.z, O[i][2]);
                O[i][3] = fmaf(p.z, v2.w, O[i][3]);
                O[i][0] = fmaf(p.w, v3.x, O[i][0]);
                O[i][1] = fmaf(p.w, v3.y, O[i][1]);
                O[i][2] = fmaf(p.w, v3.z, O[i][2]);
                O[i][3] = fmaf(p.w, v3.w, O[i][3]);
            }
        }
    }

    // epilogue: normalize and write [B,S,H*D]
    const int b = bh >> 4, h = bh & 15;
#pragma unroll
    for (int i = 0; i < 4; i++) {
        const float inv = 1.f / sml[r0 + i];
        const int s = q0 + r0 + i;
        float4 o = make_float4(O[i][0] * inv, O[i][1] * inv,
                               O[i][2] * inv, O[i][3] * inv);
        *(float4*)(out + (b * Ssq + s) * Ww + h * Dd + c0) = o;
    }
}

// ---------------------------------------------------------------------------
extern "C" void kernel_launch(void* const* d_in, const int* in_sizes, int n_in,
                              void* d_out, int out_size)
{
    const float* from_t = (const float*)d_in[0];
    const float* to_t   = (const float*)d_in[1];
    const float* Wq     = (const float*)d_in[2];
    const float* bq     = (const float*)d_in[3];
    const float* Wk     = (const float*)d_in[4];
    const float* bk     = (const float*)d_in[5];
    const float* Wv     = (const float*)d_in[6];
    const float* bv     = (const float*)d_in[7];
    float* out = (float*)d_out;

    dim3 g1(Ww / 128, (Bb * Ssq) / 128, 3);
    qkv_gemm<<<g1, 256>>>(from_t, to_t, Wq, bq, Wk, bk, Wv, bv);

    constexpr size_t smem_attn = (size_t)(3 * 4096 + 64 * 68 + 192) * sizeof(float);
    cudaFuncSetAttribute(attn_kernel,
                         cudaFuncAttributeMaxDynamicSharedMemorySize,
                         (int)smem_attn);
    dim3 g2(Ssq / 64, Bb * Hh);
    attn_kernel<<<g2, 256, smem_attn>>>(out);
}

// round 3
// speedup vs baseline: 1.4479x; 1.4479x over previous
#include <cuda_runtime.h>
#include <cstdint>

// Problem constants
#define Bb  8
#define Ssq 1024
#define Hh  16
#define Dd  64
#define Ww  1024   // hidden = H*D

// Scratch for Q/K/V in [B,H,S,D] layout
__device__ float g_q[Bb * Hh * Ssq * Dd];
__device__ float g_k[Bb * Hh * Ssq * Dd];
__device__ float g_v[Bb * Hh * Ssq * Dd];

__device__ __forceinline__ uint32_t f32_to_tf32(float f) {
    uint32_t r;
    asm("cvt.rna.tf32.f32 %0, %1;" : "=r"(r) : "f"(f));
    return r;
}

__device__ __forceinline__ void mma_tf32(float d[4], const uint32_t a[4],
                                         const uint32_t b[2]) {
    asm volatile(
        "mma.sync.aligned.m16n8k8.row.col.f32.tf32.tf32.f32 "
        "{%0,%1,%2,%3}, {%4,%5,%6,%7}, {%8,%9}, {%0,%1,%2,%3};"
        : "+f"(d[0]), "+f"(d[1]), "+f"(d[2]), "+f"(d[3])
        : "r"(a[0]), "r"(a[1]), "r"(a[2]), "r"(a[3]),
          "r"(b[0]), "r"(b[1]));
}

// ===========================================================================
// QKV projection with mma.sync tf32:
//   C[8192,1024] = A[8192,1024] @ W[1024,1024] + b  -> scatter to [B,H,S,D]
// CTA tile 128x128, 8 warps (2M x 4N), warp tile 64x32, K chunks of 16,
// double-buffered smem with reg-staged global prefetch.
// Smem stride 136 (== 8 mod 32) makes fragment LDS conflict-free.
// ===========================================================================
#define KC 16
#define NCHUNK (Ww / KC)   // 64
#define SSTR 136

__global__ __launch_bounds__(256) void qkv_gemm_mma(
    const float* __restrict__ from_t, const float* __restrict__ to_t,
    const float* __restrict__ Wq, const float* __restrict__ bq,
    const float* __restrict__ Wk, const float* __restrict__ bk,
    const float* __restrict__ Wv, const float* __restrict__ bv)
{
    __shared__ uint32_t As[2][KC][SSTR];   // A^T (k-major), tf32 bits
    __shared__ uint32_t Bs[2][KC][SSTR];   // W   (k-major), tf32 bits

    const int which = blockIdx.z;
    const float* A  = (which == 0) ? from_t : to_t;
    const float* Wm = (which == 0) ? Wq : (which == 1) ? Wk : Wv;
    const float* bbv = (which == 0) ? bq : (which == 1) ? bk : bv;
    float* outp     = (which == 0) ? g_q : (which == 1) ? g_k : g_v;

    const int tid = threadIdx.x;
    const int wid = tid >> 5;
    const int lane = tid & 31;
    const int m0 = blockIdx.y * 128;
    const int n0 = blockIdx.x * 128;

    const int wm = wid & 1;        // 0..1  -> M half
    const int wn = wid >> 1;       // 0..3  -> N quarter
    const int lq = lane >> 2;      // 0..7
    const int lr = lane & 3;       // 0..3

    // global->smem indices
    const int a_row = tid >> 1;            // 0..127
    const int a_c4  = (tid & 1) << 3;      // 0 or 8 (two float4 per row half)
    const int b_kr  = tid >> 5;            // 0..7 (per j adds 8)
    const int b_n4  = (tid & 31) << 2;     // 0..124

    float acc[4][4][4];
#pragma unroll
    for (int mi = 0; mi < 4; mi++)
#pragma unroll
        for (int nj = 0; nj < 4; nj++)
#pragma unroll
            for (int e = 0; e < 4; e++) acc[mi][nj][e] = 0.f;

    // stage chunk 0
    float4 ra[2], rb[2];
    {
        ra[0] = *(const float4*)(A + (m0 + a_row) * Ww + a_c4);
        ra[1] = *(const float4*)(A + (m0 + a_row) * Ww + a_c4 + 4);
        rb[0] = *(const float4*)(Wm + (0 + b_kr) * Ww + n0 + b_n4);
        rb[1] = *(const float4*)(Wm + (8 + b_kr) * Ww + n0 + b_n4);
    }

#pragma unroll 1
    for (int i = 0; i < NCHUNK; i++) {
        const int b = i & 1;
        // store staged regs -> smem buf b (tf32 converted)
        As[b][a_c4 + 0][a_row] = f32_to_tf32(ra[0].x);
        As[b][a_c4 + 1][a_row] = f32_to_tf32(ra[0].y);
        As[b][a_c4 + 2][a_row] = f32_to_tf32(ra[0].z);
        As[b][a_c4 + 3][a_row] = f32_to_tf32(ra[0].w);
        As[b][a_c4 + 4][a_row] = f32_to_tf32(ra[1].x);
        As[b][a_c4 + 5][a_row] = f32_to_tf32(ra[1].y);
        As[b][a_c4 + 6][a_row] = f32_to_tf32(ra[1].z);
        As[b][a_c4 + 7][a_row] = f32_to_tf32(ra[1].w);
        {
            uint4 t0, t1;
            t0.x = f32_to_tf32(rb[0].x); t0.y = f32_to_tf32(rb[0].y);
            t0.z = f32_to_tf32(rb[0].z); t0.w = f32_to_tf32(rb[0].w);
            t1.x = f32_to_tf32(rb[1].x); t1.y = f32_to_tf32(rb[1].y);
            t1.z = f32_to_tf32(rb[1].z); t1.w = f32_to_tf32(rb[1].w);
            *(uint4*)&Bs[b][b_kr][b_n4]     = t0;
            *(uint4*)&Bs[b][b_kr + 8][b_n4] = t1;
        }
        __syncthreads();

        // prefetch chunk i+1 into regs (overlaps with mma below)
        if (i + 1 < NCHUNK) {
            const int k0 = (i + 1) * KC;
            ra[0] = *(const float4*)(A + (m0 + a_row) * Ww + k0 + a_c4);
            ra[1] = *(const float4*)(A + (m0 + a_row) * Ww + k0 + a_c4 + 4);
            rb[0] = *(const float4*)(Wm + (k0 + b_kr) * Ww + n0 + b_n4);
            rb[1] = *(const float4*)(Wm + (k0 + 8 + b_kr) * Ww + n0 + b_n4);
        }

        // compute on buf b: two k=8 steps
#pragma unroll
        for (int ks = 0; ks < KC; ks += 8) {
            uint32_t af[4][4], bf[4][2];
#pragma unroll
            for (int mi = 0; mi < 4; mi++) {
                const int m = wm * 64 + mi * 16 + lq;
                af[mi][0] = As[b][ks + lr][m];
                af[mi][1] = As[b][ks + lr][m + 8];
                af[mi][2] = As[b][ks + lr + 4][m];
                af[mi][3] = As[b][ks + lr + 4][m + 8];
            }
#pragma unroll
            for (int nj = 0; nj < 4; nj++) {
                const int n = wn * 32 + nj * 8 + lq;
                bf[nj][0] = Bs[b][ks + lr][n];
                bf[nj][1] = Bs[b][ks + lr + 4][n];
            }
#pragma unroll
            for (int mi = 0; mi < 4; mi++)
#pragma unroll
                for (int nj = 0; nj < 4; nj++)
                    mma_tf32(acc[mi][nj], af[mi], bf[nj]);
        }
        __syncthreads();
    }

    // epilogue: bias + scatter to [B,H,S,D]
#pragma unroll
    for (int mi = 0; mi < 4; mi++) {
        const int mA = m0 + wm * 64 + mi * 16 + lq;
        const int mB = mA + 8;
        const int biA = mA >> 10, sA = mA & 1023;
        const int biB = mB >> 10, sB = mB & 1023;
#pragma unroll
        for (int nj = 0; nj < 4; nj++) {
            const int n = n0 + wn * 32 + nj * 8 + 2 * lr;
            const int h = n >> 6, d = n & 63;
            const float bx = __ldg(bbv + n), by = __ldg(bbv + n + 1);
            float2 v0 = make_float2(acc[mi][nj][0] + bx, acc[mi][nj][1] + by);
            float2 v1 = make_float2(acc[mi][nj][2] + bx, acc[mi][nj][3] + by);
            *(float2*)(outp + ((biA * Hh + h) * Ssq + sA) * Dd + d) = v0;
            *(float2*)(outp + ((biB * Hh + h) * Ssq + sB) * Dd + d) = v1;
        }
    }
}

// ---------------------------------------------------------------------------
// Flash attention, fp32 (unchanged; mma.sync port is next round).
// ---------------------------------------------------------------------------
__device__ __forceinline__ int swz(int k, int r) {
    return k * 64 + (r ^ (((k >> 2) & 15) << 2));
}

__global__ __launch_bounds__(256) void attn_kernel(float* __restrict__ out)
{
    extern __shared__ float sm[];
    float* Qs = sm;                 // 4096: [d][r] swizzled, pre-scaled by 1/8
    float* Ks = sm + 4096;          // 4096: [d][c] swizzled
    float* Vs = sm + 8192;          // 4096: [k][d] swizzled
    float* Ps = sm + 12288;         // 64 x 68 (scores -> probs)
    float* smm = Ps + 64 * 68;      // running max, 64
    float* sml = smm + 64;          // running sum, 64
    float* smc = sml + 64;          // per-iter correction, 64

    const int tid = threadIdx.x;
    const int bh = blockIdx.y;
    const int q0 = blockIdx.x * 64;

    const float* Qg = g_q + (bh * Ssq + q0) * Dd;
    const float* Kg = g_k + bh * Ssq * Dd;
    const float* Vg = g_v + bh * Ssq * Dd;

#pragma unroll
    for (int i = 0; i < 4; i++) {
        int c = i * 256 + tid;
        int r = c >> 4;
        int d4 = (c & 15) << 2;
        float4 v = *(const float4*)(Qg + r * 64 + d4);
        Qs[swz(d4 + 0, r)] = v.x * 0.125f;
        Qs[swz(d4 + 1, r)] = v.y * 0.125f;
        Qs[swz(d4 + 2, r)] = v.z * 0.125f;
        Qs[swz(d4 + 3, r)] = v.w * 0.125f;
    }
    if (tid < 64) { smm[tid] = -1e30f; sml[tid] = 0.f; }

    const int ty = tid >> 4, tx = tid & 15;
    const int r0 = ty * 4, c0 = tx * 4;

    float O[4][4];
#pragma unroll
    for (int i = 0; i < 4; i++)
#pragma unroll
        for (int j = 0; j < 4; j++) O[i][j] = 0.f;

    for (int kt = 0; kt < 16; kt++) {
        const float* Kt = Kg + kt * 64 * 64;
        const float* Vt = Vg + kt * 64 * 64;
        __syncthreads();

#pragma unroll
        for (int i = 0; i < 4; i++) {
            int c = i * 256 + tid;
            int r = c >> 4;
            int d4 = (c & 15) << 2;
            float4 kv = *(const float4*)(Kt + r * 64 + d4);
            Ks[swz(d4 + 0, r)] = kv.x;
            Ks[swz(d4 + 1, r)] = kv.y;
            Ks[swz(d4 + 2, r)] = kv.z;
            Ks[swz(d4 + 3, r)] = kv.w;
            float4 vv = *(const float4*)(Vt + r * 64 + d4);
            *(float4*)&Vs[r * 64 + (d4 ^ (((r >> 2) & 15) << 2))] = vv;
        }
        __syncthreads();

        float acc[4][4];
#pragma unroll
        for (int i = 0; i < 4; i++)
#pragma unroll
            for (int j = 0; j < 4; j++) acc[i][j] = 0.f;
#pragma unroll 8
        for (int kk = 0; kk < 64; kk++) {
            const int cs = ((kk >> 2) & 15) << 2;
            float4 q = *(const float4*)&Qs[kk * 64 + (r0 ^ cs)];
            float4 k = *(const float4*)&Ks[kk * 64 + (c0 ^ cs)];
            float qa[4] = {q.x, q.y, q.z, q.w};
            float ka[4] = {k.x, k.y, k.z, k.w};
#pragma unroll
            for (int i = 0; i < 4; i++)
#pragma unroll
                for (int j = 0; j < 4; j++)
                    acc[i][j] = fmaf(qa[i], ka[j], acc[i][j]);
        }
#pragma unroll
        for (int i = 0; i < 4; i++) {
            float4 v = make_float4(acc[i][0], acc[i][1], acc[i][2], acc[i][3]);
            *(float4*)&Ps[(r0 + i) * 68 + c0] = v;
        }
        __syncthreads();

        {
            const int row = tid >> 2, jj = tid & 3;
            const float m_old = smm[row];
            float pv[16];
            float lm = -1e30f;
#pragma unroll
            for (int e = 0; e < 16; e++) {
                pv[e] = Ps[row * 68 + jj * 16 + e];
                lm = fmaxf(lm, pv[e]);
            }
            lm = fmaxf(lm, __shfl_xor_sync(0xffffffffu, lm, 1));
            lm = fmaxf(lm, __shfl_xor_sync(0xffffffffu, lm, 2));
            const float mnew = fmaxf(m_old, lm);
            float lsum = 0.f;
#pragma unroll
            for (int e = 0; e < 16; e++) {
                float p = __expf(pv[e] - mnew);
                lsum += p;
                Ps[row * 68 + jj * 16 + e] = p;
            }
            lsum += __shfl_xor_sync(0xffffffffu, lsum, 1);
            lsum += __shfl_xor_sync(0xffffffffu, lsum, 2);
            if (jj == 0) {
                smc[row] = __expf(m_old - mnew);
                sml[row] = sml[row] * smc[row] + lsum;
                smm[row] = mnew;
            }
        }
        __syncthreads();

#pragma unroll
        for (int i = 0; i < 4; i++) {
            const float cr = smc[r0 + i];
#pragma unroll
            for (int j = 0; j < 4; j++) O[i][j] *= cr;
        }
#pragma unroll 2
        for (int kk = 0; kk < 64; kk += 4) {
            const int cs = ((kk >> 2) & 15) << 2;
            float4 v0 = *(const float4*)&Vs[(kk + 0) * 64 + (c0 ^ cs)];
            float4 v1 = *(const float4*)&Vs[(kk + 1) * 64 + (c0 ^ cs)];
            float4 v2 = *(const float4*)&Vs[(kk + 2) * 64 + (c0 ^ cs)];
            float4 v3 = *(const float4*)&Vs[(kk + 3) * 64 + (c0 ^ cs)];
#pragma unroll
            for (int i = 0; i < 4; i++) {
                float4 p = *(const float4*)&Ps[(r0 + i) * 68 + kk];
                O[i][0] = fmaf(p.x, v0.x, O[i][0]);
                O[i][1] = fmaf(p.x, v0.y, O[i][1]);
                O[i][2] = fmaf(p.x, v0.z, O[i][2]);
                O[i][3] = fmaf(p.x, v0.w, O[i][3]);
                O[i][0] = fmaf(p.y, v1.x, O[i][0]);
                O[i][1] = fmaf(p.y, v1.y, O[i][1]);
                O[i][2] = fmaf(p.y, v1.z, O[i][2]);
                O[i][3] = fmaf(p.y, v1.w, O[i][3]);
                O[i][0] = fmaf(p.z, v2.x, O[i][0]);
                O[i][1] = fmaf(p.z, v2.y, O[i][1]);
                O[i][2] = fmaf(p.z, v2.z, O[i][2]);
                O[i][3] = fmaf(p.z, v2.w, O[i][3]);
                O[i][0] = fmaf(p.w, v3.x, O[i][0]);
                O[i][1] = fmaf(p.w, v3.y, O[i][1]);
                O[i][2] = fmaf(p.w, v3.z, O[i][2]);
                O[i][3] = fmaf(p.w, v3.w, O[i][3]);
            }
        }
    }

    const int b = bh >> 4, h = bh & 15;
#pragma unroll
    for (int i = 0; i < 4; i++) {
        const float inv = 1.f / sml[r0 + i];
        const int s = q0 + r0 + i;
        float4 o = make_float4(O[i][0] * inv, O[i][1] * inv,
                               O[i][2] * inv, O[i][3] * inv);
        *(float4*)(out + (b * Ssq + s) * Ww + h * Dd + c0) = o;
    }
}

// ---------------------------------------------------------------------------
extern "C" void kernel_launch(void* const* d_in, const int* in_sizes, int n_in,
                              void* d_out, int out_size)
{
    const float* from_t = (const float*)d_in[0];
    const float* to_t   = (const float*)d_in[1];
    const float* Wq     = (const float*)d_in[2];
    const float* bq     = (const float*)d_in[3];
    const float* Wk     = (const float*)d_in[4];
    const float* bk     = (const float*)d_in[5];
    const float* Wv     = (const float*)d_in[6];
    const float* bv     = (const float*)d_in[7];
    float* out = (float*)d_out;

    dim3 g1(Ww / 128, (Bb * Ssq) / 128, 3);
    qkv_gemm_mma<<<g1, 256>>>(from_t, to_t, Wq, bq, Wk, bk, Wv, bv);

    constexpr size_t smem_attn = (size_t)(3 * 4096 + 64 * 68 + 192) * sizeof(float);
    cudaFuncSetAttribute(attn_kernel,
                         cudaFuncAttributeMaxDynamicSharedMemorySize,
                         (int)smem_attn);
    dim3 g2(Ssq / 64, Bb * Hh);
    attn_kernel<<<g2, 256, smem_attn>>>(out);
}

// round 4
// speedup vs baseline: 2.7789x; 1.9193x over previous
#include <cuda_runtime.h>
#include <cuda_fp16.h>
#include <cstdint>

// Problem constants
#define Bb  8
#define Ssq 1024
#define Hh  16
#define Dd  64
#define Ww  1024   // hidden = H*D

// Scratch for Q/K/V in [B,H,S,D] layout
__device__ float g_q[Bb * Hh * Ssq * Dd];
__device__ float g_k[Bb * Hh * Ssq * Dd];
__device__ float g_v[Bb * Hh * Ssq * Dd];

__device__ __forceinline__ uint32_t f32_to_tf32(float f) {
    uint32_t r;
    asm("cvt.rna.tf32.f32 %0, %1;" : "=r"(r) : "f"(f));
    return r;
}

__device__ __forceinline__ float ex2(float x) {
    float y;
    asm("ex2.approx.f32 %0, %1;" : "=f"(y) : "f"(x));
    return y;
}

__device__ __forceinline__ void mma_tf32(float d[4], const uint32_t a[4],
                                         uint32_t b0, uint32_t b1) {
    asm volatile(
        "mma.sync.aligned.m16n8k8.row.col.f32.tf32.tf32.f32 "
        "{%0,%1,%2,%3}, {%4,%5,%6,%7}, {%8,%9}, {%0,%1,%2,%3};"
        : "+f"(d[0]), "+f"(d[1]), "+f"(d[2]), "+f"(d[3])
        : "r"(a[0]), "r"(a[1]), "r"(a[2]), "r"(a[3]),
          "r"(b0), "r"(b1));
}

__device__ __forceinline__ void mma_f16(float d[4], uint32_t a0, uint32_t a1,
                                        uint32_t a2, uint32_t a3,
                                        uint32_t b0, uint32_t b1) {
    asm volatile(
        "mma.sync.aligned.m16n8k16.row.col.f32.f16.f16.f32 "
        "{%0,%1,%2,%3}, {%4,%5,%6,%7}, {%8,%9}, {%0,%1,%2,%3};"
        : "+f"(d[0]), "+f"(d[1]), "+f"(d[2]), "+f"(d[3])
        : "r"(a0), "r"(a1), "r"(a2), "r"(a3), "r"(b0), "r"(b1));
}

// ===========================================================================
// QKV projection with mma.sync tf32 (unchanged from round 3).
// ===========================================================================
#define KC 16
#define NCHUNK (Ww / KC)   // 64
#define SSTR 136

__global__ __launch_bounds__(256) void qkv_gemm_mma(
    const float* __restrict__ from_t, const float* __restrict__ to_t,
    const float* __restrict__ Wq, const float* __restrict__ bq,
    const float* __restrict__ Wk, const float* __restrict__ bk,
    const float* __restrict__ Wv, const float* __restrict__ bv)
{
    __shared__ uint32_t As[2][KC][SSTR];
    __shared__ uint32_t Bs[2][KC][SSTR];

    const int which = blockIdx.z;
    const float* A  = (which == 0) ? from_t : to_t;
    const float* Wm = (which == 0) ? Wq : (which == 1) ? Wk : Wv;
    const float* bbv = (which == 0) ? bq : (which == 1) ? bk : bv;
    float* outp     = (which == 0) ? g_q : (which == 1) ? g_k : g_v;

    const int tid = threadIdx.x;
    const int wid = tid >> 5;
    const int lane = tid & 31;
    const int m0 = blockIdx.y * 128;
    const int n0 = blockIdx.x * 128;

    const int wm = wid & 1;
    const int wn = wid >> 1;
    const int lq = lane >> 2;
    const int lr = lane & 3;

    const int a_row = tid >> 1;
    const int a_c4  = (tid & 1) << 3;
    const int b_kr  = tid >> 5;
    const int b_n4  = (tid & 31) << 2;

    float acc[4][4][4];
#pragma unroll
    for (int mi = 0; mi < 4; mi++)
#pragma unroll
        for (int nj = 0; nj < 4; nj++)
#pragma unroll
            for (int e = 0; e < 4; e++) acc[mi][nj][e] = 0.f;

    float4 ra[2], rb[2];
    ra[0] = *(const float4*)(A + (m0 + a_row) * Ww + a_c4);
    ra[1] = *(const float4*)(A + (m0 + a_row) * Ww + a_c4 + 4);
    rb[0] = *(const float4*)(Wm + (0 + b_kr) * Ww + n0 + b_n4);
    rb[1] = *(const float4*)(Wm + (8 + b_kr) * Ww + n0 + b_n4);

#pragma unroll 1
    for (int i = 0; i < NCHUNK; i++) {
        const int b = i & 1;
        As[b][a_c4 + 0][a_row] = f32_to_tf32(ra[0].x);
        As[b][a_c4 + 1][a_row] = f32_to_tf32(ra[0].y);
        As[b][a_c4 + 2][a_row] = f32_to_tf32(ra[0].z);
        As[b][a_c4 + 3][a_row] = f32_to_tf32(ra[0].w);
        As[b][a_c4 + 4][a_row] = f32_to_tf32(ra[1].x);
        As[b][a_c4 + 5][a_row] = f32_to_tf32(ra[1].y);
        As[b][a_c4 + 6][a_row] = f32_to_tf32(ra[1].z);
        As[b][a_c4 + 7][a_row] = f32_to_tf32(ra[1].w);
        {
            uint4 t0, t1;
            t0.x = f32_to_tf32(rb[0].x); t0.y = f32_to_tf32(rb[0].y);
            t0.z = f32_to_tf32(rb[0].z); t0.w = f32_to_tf32(rb[0].w);
            t1.x = f32_to_tf32(rb[1].x); t1.y = f32_to_tf32(rb[1].y);
            t1.z = f32_to_tf32(rb[1].z); t1.w = f32_to_tf32(rb[1].w);
            *(uint4*)&Bs[b][b_kr][b_n4]     = t0;
            *(uint4*)&Bs[b][b_kr + 8][b_n4] = t1;
        }
        __syncthreads();

        if (i + 1 < NCHUNK) {
            const int k0 = (i + 1) * KC;
            ra[0] = *(const float4*)(A + (m0 + a_row) * Ww + k0 + a_c4);
            ra[1] = *(const float4*)(A + (m0 + a_row) * Ww + k0 + a_c4 + 4);
            rb[0] = *(const float4*)(Wm + (k0 + b_kr) * Ww + n0 + b_n4);
            rb[1] = *(const float4*)(Wm + (k0 + 8 + b_kr) * Ww + n0 + b_n4);
        }

#pragma unroll
        for (int ks = 0; ks < KC; ks += 8) {
            uint32_t af[4][4], bf[4][2];
#pragma unroll
            for (int mi = 0; mi < 4; mi++) {
                const int m = wm * 64 + mi * 16 + lq;
                af[mi][0] = As[b][ks + lr][m];
                af[mi][1] = As[b][ks + lr][m + 8];
                af[mi][2] = As[b][ks + lr + 4][m];
                af[mi][3] = As[b][ks + lr + 4][m + 8];
            }
#pragma unroll
            for (int nj = 0; nj < 4; nj++) {
                const int n = wn * 32 + nj * 8 + lq;
                bf[nj][0] = Bs[b][ks + lr][n];
                bf[nj][1] = Bs[b][ks + lr + 4][n];
            }
#pragma unroll
            for (int mi = 0; mi < 4; mi++)
#pragma unroll
                for (int nj = 0; nj < 4; nj++)
                    mma_tf32(acc[mi][nj], af[mi], bf[nj][0], bf[nj][1]);
        }
        __syncthreads();
    }

#pragma unroll
    for (int mi = 0; mi < 4; mi++) {
        const int mA = m0 + wm * 64 + mi * 16 + lq;
        const int mB = mA + 8;
        const int biA = mA >> 10, sA = mA & 1023;
        const int biB = mB >> 10, sB = mB & 1023;
#pragma unroll
        for (int nj = 0; nj < 4; nj++) {
            const int n = n0 + wn * 32 + nj * 8 + 2 * lr;
            const int h = n >> 6, d = n & 63;
            const float bx = __ldg(bbv + n), by = __ldg(bbv + n + 1);
            float2 v0 = make_float2(acc[mi][nj][0] + bx, acc[mi][nj][1] + by);
            float2 v1 = make_float2(acc[mi][nj][2] + bx, acc[mi][nj][3] + by);
            *(float2*)(outp + ((biA * Hh + h) * Ssq + sA) * Dd + d) = v0;
            *(float2*)(outp + ((biB * Hh + h) * Ssq + sB) * Dd + d) = v1;
        }
    }
}

// ===========================================================================
// Flash attention with mma.sync:
//   QK^T in tf32 (m16n8k8), softmax in registers, PV in fp16 (m16n8k16).
// Br=128 (8 warps x 16 rows, FA2 partition), Bc=64, 16 K-tiles.
// Q prescaled by log2(e)/8 so softmax uses ex2 directly.
// smem: Qs[128][68] u32 | Ks[64][68] u32 | VsT[64][72] half  = 61440 B
// ===========================================================================
#define QSCALE 0.1803368801111204f   // log2(e) / 8

__global__ __launch_bounds__(256) void attn_mma(float* __restrict__ out)
{
    extern __shared__ char smraw[];
    uint32_t* Qs = (uint32_t*)smraw;                    // [128][68]
    uint32_t* Ks = (uint32_t*)(smraw + 34816);          // [64][68]
    __half*   Vs = (__half*)  (smraw + 52224);          // [64][72] transposed [d][s]

    const int tid = threadIdx.x;
    const int wid = tid >> 5;           // 0..7 -> row block
    const int lane = tid & 31;
    const int g = lane >> 2;            // 0..7
    const int t = lane & 3;             // 0..3

    const int bh = blockIdx.y;          // b*16 + h
    const int q0 = blockIdx.x * 128;

    const float* Qg = g_q + (bh * Ssq + q0) * Dd;
    const float* Kg = g_k + bh * Ssq * Dd;
    const float* Vg = g_v + bh * Ssq * Dd;

    // load Q tile (128x64), scale, convert tf32
    {
        const int m = tid >> 1;
        const int dbase = (tid & 1) * 32;
#pragma unroll
        for (int j = 0; j < 8; j++) {
            float4 v = *(const float4*)(Qg + m * Dd + dbase + 4 * j);
            uint32_t* dst = &Qs[m * 68 + dbase + 4 * j];
            dst[0] = f32_to_tf32(v.x * QSCALE);
            dst[1] = f32_to_tf32(v.y * QSCALE);
            dst[2] = f32_to_tf32(v.z * QSCALE);
            dst[3] = f32_to_tf32(v.w * QSCALE);
        }
    }

    float m0 = -1e30f, m1 = -1e30f, l0 = 0.f, l1 = 0.f;
    float accO[8][4];
#pragma unroll
    for (int d = 0; d < 8; d++)
#pragma unroll
        for (int e = 0; e < 4; e++) accO[d][e] = 0.f;

    const int ls = tid >> 2;            // 0..63 (K/V load row)
    const int ldb = (tid & 3) * 16;     // 0..48 (K/V load col base)

#pragma unroll 1
    for (int kt = 0; kt < 16; kt++) {
        const float* Kt = Kg + kt * 64 * 64;
        const float* Vt = Vg + kt * 64 * 64;

        __syncthreads();   // previous tile fully consumed
#pragma unroll
        for (int j = 0; j < 4; j++) {
            const int d = ldb + 4 * j;
            float4 kv = *(const float4*)(Kt + ls * 64 + d);
            uint32_t* dst = &Ks[ls * 68 + d];
            dst[0] = f32_to_tf32(kv.x);
            dst[1] = f32_to_tf32(kv.y);
            dst[2] = f32_to_tf32(kv.z);
            dst[3] = f32_to_tf32(kv.w);
            float4 vv = *(const float4*)(Vt + ls * 64 + d);
            Vs[(d + 0) * 72 + ls] = __float2half(vv.x);
            Vs[(d + 1) * 72 + ls] = __float2half(vv.y);
            Vs[(d + 2) * 72 + ls] = __float2half(vv.z);
            Vs[(d + 3) * 72 + ls] = __float2half(vv.w);
        }
        __syncthreads();

        // ---- S = Q K^T  (tf32), warp rows wid*16 .. +15, keys 0..63 ----
        float accs[8][4];
#pragma unroll
        for (int j = 0; j < 8; j++)
#pragma unroll
            for (int e = 0; e < 4; e++) accs[j][e] = 0.f;

#pragma unroll
        for (int ks = 0; ks < 8; ks++) {
            uint32_t a[4];
            const int mrow = wid * 16 + g;
            a[0] = Qs[mrow * 68 + 8 * ks + t];
            a[1] = Qs[(mrow + 8) * 68 + 8 * ks + t];
            a[2] = Qs[mrow * 68 + 8 * ks + t + 4];
            a[3] = Qs[(mrow + 8) * 68 + 8 * ks + t + 4];
#pragma unroll
            for (int j = 0; j < 8; j++) {
                uint32_t b0 = Ks[(8 * j + g) * 68 + 8 * ks + t];
                uint32_t b1 = Ks[(8 * j + g) * 68 + 8 * ks + t + 4];
                mma_tf32(accs[j], a, b0, b1);
            }
        }

        // ---- online softmax (rows g and g+8 of this warp's slice) ----
        float mx0 = -1e30f, mx1 = -1e30f;
#pragma unroll
        for (int j = 0; j < 8; j++) {
            mx0 = fmaxf(mx0, fmaxf(accs[j][0], accs[j][1]));
            mx1 = fmaxf(mx1, fmaxf(accs[j][2], accs[j][3]));
        }
        mx0 = fmaxf(mx0, __shfl_xor_sync(0xffffffffu, mx0, 1));
        mx0 = fmaxf(mx0, __shfl_xor_sync(0xffffffffu, mx0, 2));
        mx1 = fmaxf(mx1, __shfl_xor_sync(0xffffffffu, mx1, 1));
        mx1 = fmaxf(mx1, __shfl_xor_sync(0xffffffffu, mx1, 2));

        const float mn0 = fmaxf(m0, mx0);
        const float mn1 = fmaxf(m1, mx1);
        const float c0 = ex2(m0 - mn0);
        const float c1 = ex2(m1 - mn1);

        float s0 = 0.f, s1 = 0.f;
#pragma unroll
        for (int j = 0; j < 8; j++) {
            accs[j][0] = ex2(accs[j][0] - mn0); s0 += accs[j][0];
            accs[j][1] = ex2(accs[j][1] - mn0); s0 += accs[j][1];
            accs[j][2] = ex2(accs[j][2] - mn1); s1 += accs[j][2];
            accs[j][3] = ex2(accs[j][3] - mn1); s1 += accs[j][3];
        }
        s0 += __shfl_xor_sync(0xffffffffu, s0, 1);
        s0 += __shfl_xor_sync(0xffffffffu, s0, 2);
        s1 += __shfl_xor_sync(0xffffffffu, s1, 1);
        s1 += __shfl_xor_sync(0xffffffffu, s1, 2);

        l0 = l0 * c0 + s0;
        l1 = l1 * c1 + s1;
        m0 = mn0;
        m1 = mn1;

#pragma unroll
        for (int d = 0; d < 8; d++) {
            accO[d][0] *= c0; accO[d][1] *= c0;
            accO[d][2] *= c1; accO[d][3] *= c1;
        }

        // ---- O += P V  (fp16 m16n8k16, P from accs registers) ----
#pragma unroll
        for (int kb = 0; kb < 4; kb++) {
            __half2 h0 = __float22half2_rn(make_float2(accs[2*kb][0],   accs[2*kb][1]));
            __half2 h1 = __float22half2_rn(make_float2(accs[2*kb][2],   accs[2*kb][3]));
            __half2 h2 = __float22half2_rn(make_float2(accs[2*kb+1][0], accs[2*kb+1][1]));
            __half2 h3 = __float22half2_rn(make_float2(accs[2*kb+1][2], accs[2*kb+1][3]));
            uint32_t pa0 = *(uint32_t*)&h0;
            uint32_t pa1 = *(uint32_t*)&h1;
            uint32_t pa2 = *(uint32_t*)&h2;
            uint32_t pa3 = *(uint32_t*)&h3;
#pragma unroll
            for (int db = 0; db < 8; db++) {
                const int drow = (8 * db + g) * 72 + 16 * kb + 2 * t;
                uint32_t b0 = *(const uint32_t*)&Vs[drow];
                uint32_t b1 = *(const uint32_t*)&Vs[drow + 8];
                mma_f16(accO[db], pa0, pa1, pa2, pa3, b0, b1);
            }
        }
    }

    // ---- epilogue: normalize and write [B,S,H*D] ----
    const int b = bh >> 4, h = bh & 15;
    const float inv0 = 1.f / l0;
    const float inv1 = 1.f / l1;
    const int row0 = q0 + wid * 16 + g;
    const int row1 = row0 + 8;
#pragma unroll
    for (int db = 0; db < 8; db++) {
        const int d = db * 8 + 2 * t;
        float2 v0 = make_float2(accO[db][0] * inv0, accO[db][1] * inv0);
        float2 v1 = make_float2(accO[db][2] * inv1, accO[db][3] * inv1);
        *(float2*)(out + (b * Ssq + row0) * Ww + h * Dd + d) = v0;
        *(float2*)(out + (b * Ssq + row1) * Ww + h * Dd + d) = v1;
    }
}

// ---------------------------------------------------------------------------
extern "C" void kernel_launch(void* const* d_in, const int* in_sizes, int n_in,
                              void* d_out, int out_size)
{
    const float* from_t = (const float*)d_in[0];
    const float* to_t   = (const float*)d_in[1];
    const float* Wq     = (const float*)d_in[2];
    const float* bq     = (const float*)d_in[3];
    const float* Wk     = (const float*)d_in[4];
    const float* bk     = (const float*)d_in[5];
    const float* Wv     = (const float*)d_in[6];
    const float* bv     = (const float*)d_in[7];
    float* out = (float*)d_out;

    dim3 g1(Ww / 128, (Bb * Ssq) / 128, 3);
    qkv_gemm_mma<<<g1, 256>>>(from_t, to_t, Wq, bq, Wk, bk, Wv, bv);

    constexpr int smem_attn = 61440;
    cudaFuncSetAttribute(attn_mma,
                         cudaFuncAttributeMaxDynamicSharedMemorySize,
                         smem_attn);
    dim3 g2(Ssq / 128, Bb * Hh);
    attn_mma<<<g2, 256, smem_attn>>>(out);
}

// round 5
// speedup vs baseline: 4.1614x; 1.4975x over previous
#include <cuda_runtime.h>
#include <cuda_fp16.h>
#include <cstdint>

// Problem constants
#define Bb  8
#define Ssq 1024
#define Hh  16
#define Dd  64
#define Ww  1024   // hidden = H*D

#define QSCALE 0.1803368801111204f   // log2(e) / 8

// fp16 copies of inputs (one-time convert pass)
__device__ __half g_fh[Bb * Ssq * Ww];        // from_tensor fp16
__device__ __half g_th[Bb * Ssq * Ww];        // to_tensor fp16
__device__ __half g_wh[3 * Ww * Ww];          // Wq|Wk|Wv fp16

// Q/K/V in [B,H,S,D] fp16 (Q pre-scaled by QSCALE)
__device__ __half g_qh[Bb * Hh * Ssq * Dd];
__device__ __half g_kh[Bb * Hh * Ssq * Dd];
__device__ __half g_vh[Bb * Hh * Ssq * Dd];

__device__ __forceinline__ float ex2(float x) {
    float y;
    asm("ex2.approx.f32 %0, %1;" : "=f"(y) : "f"(x));
    return y;
}

__device__ __forceinline__ void mma_f16(float d[4], uint32_t a0, uint32_t a1,
                                        uint32_t a2, uint32_t a3,
                                        uint32_t b0, uint32_t b1) {
    asm volatile(
        "mma.sync.aligned.m16n8k16.row.col.f32.f16.f16.f32 "
        "{%0,%1,%2,%3}, {%4,%5,%6,%7}, {%8,%9}, {%0,%1,%2,%3};"
        : "+f"(d[0]), "+f"(d[1]), "+f"(d[2]), "+f"(d[3])
        : "r"(a0), "r"(a1), "r"(a2), "r"(a3), "r"(b0), "r"(b1));
}

// ===========================================================================
// One-time f32 -> fp16 convert of all inputs. 4 elems per thread.
// Segments (in 4-elem groups): from 2097152 | to 2097152 | Wq/Wk/Wv 262144 ea.
// ===========================================================================
#define CVT_GROUPS 4980736
__global__ __launch_bounds__(256) void cvt_all(
    const float* __restrict__ from_t, const float* __restrict__ to_t,
    const float* __restrict__ Wq, const float* __restrict__ Wk,
    const float* __restrict__ Wv)
{
    long gidx = (long)blockIdx.x * 256 + threadIdx.x;
    const float* src;
    __half* dst;
    long off;
    if (gidx < 2097152)      { src = from_t; dst = g_fh; off = gidx; }
    else if (gidx < 4194304) { src = to_t;   dst = g_th; off = gidx - 2097152; }
    else if (gidx < 4456448) { src = Wq; dst = g_wh;               off = gidx - 4194304; }
    else if (gidx < 4718592) { src = Wk; dst = g_wh + Ww * Ww;     off = gidx - 4456448; }
    else                     { src = Wv; dst = g_wh + 2 * Ww * Ww; off = gidx - 4718592; }
    float4 v = *(const float4*)(src + off * 4);
    __half2 h0 = __float22half2_rn(make_float2(v.x, v.y));
    __half2 h1 = __float22half2_rn(make_float2(v.z, v.w));
    *(uint2*)(dst + off * 4) = make_uint2(*(uint32_t*)&h0, *(uint32_t*)&h1);
}

// ===========================================================================
// QKV projection, fp16 mma m16n8k16:
//   C[8192,1024] = A @ W + b  -> fp16 scatter to [B,H,S,D] (Q scaled).
// CTA tile 128x128, 8 warps (2M x 4N), warp 64x32, K chunks of 32 (k2=16),
// double buffered. smem [k2][m]/[k2][n] as half2(u32), stride 136.
// ===========================================================================
#define KC2 16            // half2 rows per chunk (K=32)
#define NCH 32            // 1024 / 32
#define SSTR 136

__global__ __launch_bounds__(256) void qkv_gemm_h(
    const float* __restrict__ bq, const float* __restrict__ bk,
    const float* __restrict__ bv)
{
    __shared__ uint32_t As[2][KC2][SSTR];
    __shared__ uint32_t Bs[2][KC2][SSTR];

    const int which = blockIdx.z;
    const __half* A  = (which == 0) ? g_fh : g_th;
    const __half* Wm = g_wh + which * (Ww * Ww);
    const float* bbv = (which == 0) ? bq : (which == 1) ? bk : bv;
    __half* outp     = (which == 0) ? g_qh : (which == 1) ? g_kh : g_vh;
    const float sc   = (which == 0) ? QSCALE : 1.0f;

    const int tid = threadIdx.x;
    const int wid = tid >> 5;
    const int lane = tid & 31;
    const int m0 = blockIdx.y * 128;
    const int n0 = blockIdx.x * 128;

    const int wm = wid & 1;
    const int wn = wid >> 1;
    const int lq = lane >> 2;      // g
    const int lr = lane & 3;       // t

    // loaders
    const int a_row = tid & 127;
    const int a_k2b = (tid >> 7) * 8;     // 0 or 8 (constant per warp)
    const int b_k2  = tid >> 4;           // 0..15
    const int b_n   = (tid & 15) * 8;

    float acc[4][4][4];
#pragma unroll
    for (int mi = 0; mi < 4; mi++)
#pragma unroll
        for (int nj = 0; nj < 4; nj++)
#pragma unroll
            for (int e = 0; e < 4; e++) acc[mi][nj][e] = 0.f;

    uint4 la0, la1, lb0, lb1;
    la0 = *(const uint4*)(A + (m0 + a_row) * Ww + a_k2b * 2);
    la1 = *(const uint4*)(A + (m0 + a_row) * Ww + a_k2b * 2 + 8);
    lb0 = *(const uint4*)(Wm + (2 * b_k2) * Ww + n0 + b_n);
    lb1 = *(const uint4*)(Wm + (2 * b_k2 + 1) * Ww + n0 + b_n);

#pragma unroll 1
    for (int i = 0; i < NCH; i++) {
        const int b = i & 1;
        // A: 8 conflict-free 32-bit stores
        {
            const uint32_t* pa0 = (const uint32_t*)&la0;
            const uint32_t* pa1 = (const uint32_t*)&la1;
#pragma unroll
            for (int j = 0; j < 4; j++) {
                As[b][a_k2b + j][a_row]     = pa0[j];
                As[b][a_k2b + 4 + j][a_row] = pa1[j];
            }
        }
        // B: pack two k-rows into half2, 2x uint4 stores
        {
            const __half* p0 = (const __half*)&lb0;
            const __half* p1 = (const __half*)&lb1;
            uint32_t pk0[4], pk1[4];
#pragma unroll
            for (int j = 0; j < 4; j++) {
                __half2 h = __halves2half2(p0[j], p1[j]);
                pk0[j] = *(uint32_t*)&h;
            }
#pragma unroll
            for (int j = 0; j < 4; j++) {
                __half2 h = __halves2half2(p0[4 + j], p1[4 + j]);
                pk1[j] = *(uint32_t*)&h;
            }
            *(uint4*)&Bs[b][b_k2][b_n]     = *(uint4*)pk0;
            *(uint4*)&Bs[b][b_k2][b_n + 4] = *(uint4*)pk1;
        }
        __syncthreads();

        if (i + 1 < NCH) {
            const int k0 = (i + 1) * 32;
            la0 = *(const uint4*)(A + (m0 + a_row) * Ww + k0 + a_k2b * 2);
            la1 = *(const uint4*)(A + (m0 + a_row) * Ww + k0 + a_k2b * 2 + 8);
            lb0 = *(const uint4*)(Wm + (k0 + 2 * b_k2) * Ww + n0 + b_n);
            lb1 = *(const uint4*)(Wm + (k0 + 2 * b_k2 + 1) * Ww + n0 + b_n);
        }

#pragma unroll
        for (int ks2 = 0; ks2 < KC2; ks2 += 8) {
            uint32_t af[4][4], bf[4][2];
#pragma unroll
            for (int mi = 0; mi < 4; mi++) {
                const int m = wm * 64 + mi * 16 + lq;
                af[mi][0] = As[b][ks2 + lr][m];
                af[mi][1] = As[b][ks2 + lr][m + 8];
                af[mi][2] = As[b][ks2 + lr + 4][m];
                af[mi][3] = As[b][ks2 + lr + 4][m + 8];
            }
#pragma unroll
            for (int nj = 0; nj < 4; nj++) {
                const int n = wn * 32 + nj * 8 + lq;
                bf[nj][0] = Bs[b][ks2 + lr][n];
                bf[nj][1] = Bs[b][ks2 + lr + 4][n];
            }
#pragma unroll
            for (int mi = 0; mi < 4; mi++)
#pragma unroll
                for (int nj = 0; nj < 4; nj++)
                    mma_f16(acc[mi][nj], af[mi][0], af[mi][1], af[mi][2],
                            af[mi][3], bf[nj][0], bf[nj][1]);
        }
        __syncthreads();
    }

    // epilogue: bias (+scale for Q), fp16 scatter to [B,H,S,D]
#pragma unroll
    for (int mi = 0; mi < 4; mi++) {
        const int mA = m0 + wm * 64 + mi * 16 + lq;
        const int mB = mA + 8;
        const int biA = mA >> 10, sA = mA & 1023;
        const int biB = mB >> 10, sB = mB & 1023;
#pragma unroll
        for (int nj = 0; nj < 4; nj++) {
            const int n = n0 + wn * 32 + nj * 8 + 2 * lr;
            const int h = n >> 6, d = n & 63;
            const float bx = __ldg(bbv + n), by = __ldg(bbv + n + 1);
            __half2 v0 = __float22half2_rn(make_float2(
                (acc[mi][nj][0] + bx) * sc, (acc[mi][nj][1] + by) * sc));
            __half2 v1 = __float22half2_rn(make_float2(
                (acc[mi][nj][2] + bx) * sc, (acc[mi][nj][3] + by) * sc));
            *(__half2*)(outp + ((biA * Hh + h) * Ssq + sA) * Dd + d) = v0;
            *(__half2*)(outp + ((biB * Hh + h) * Ssq + sB) * Dd + d) = v1;
        }
    }
}

// ===========================================================================
// Flash attention, all-fp16 mma (m16n8k16 for QK^T and PV).
// Br=128 (8 warps x 16 rows), Bc=64, 16 K-tiles. Q pre-scaled (ex2 softmax).
// smem: Qs2[32][136] u32 (17408B) | Ks2[32][72] u32 (9216B) | Vs[64][72] half
// total 35840 B.
// ===========================================================================
__global__ __launch_bounds__(256) void attn_h(float* __restrict__ out)
{
    extern __shared__ char smraw[];
    uint32_t* Qs = (uint32_t*)smraw;              // [k2=32][136]
    uint32_t* Ks = (uint32_t*)(smraw + 17408);    // [k2=32][72]
    __half*   Vs = (__half*)  (smraw + 26624);    // [d=64][72]

    const int tid = threadIdx.x;
    const int wid = tid >> 5;
    const int lane = tid & 31;
    const int g = lane >> 2;
    const int t = lane & 3;

    const int bh = blockIdx.y;
    const int q0 = blockIdx.x * 128;

    const __half* Qg = g_qh + (bh * Ssq + q0) * Dd;
    const __half* Kg = g_kh + bh * Ssq * Dd;
    const __half* Vg = g_vh + bh * Ssq * Dd;

    // load Q tile (128 x 64 half) -> Qs[k2][m], conflict-free stores
    {
        const int m = tid & 127;
        const int k2b = (tid >> 7) * 16;   // 0 or 16 (constant per warp)
#pragma unroll
        for (int u = 0; u < 4; u++) {
            uint4 v = *(const uint4*)(Qg + m * Dd + k2b * 2 + u * 8);
            const uint32_t* pv = (const uint32_t*)&v;
#pragma unroll
            for (int j = 0; j < 4; j++)
                Qs[(k2b + u * 4 + j) * 136 + m] = pv[j];
        }
    }

    float m0 = -1e30f, m1 = -1e30f, l0 = 0.f, l1 = 0.f;
    float accO[8][4];
#pragma unroll
    for (int d = 0; d < 8; d++)
#pragma unroll
        for (int e = 0; e < 4; e++) accO[d][e] = 0.f;

    const int ls = tid & 63;           // K/V row (constant banks per warp)
    const int dg8 = (tid >> 6) * 8;    // k2 group base 0/8/16/24
    const int d0 = dg8 * 2;            // d base 0/16/32/48

#pragma unroll 1
    for (int kt = 0; kt < 16; kt++) {
        const __half* Kt = Kg + kt * 64 * 64;
        const __half* Vt = Vg + kt * 64 * 64;

        __syncthreads();
        {
            uint4 kv0 = *(const uint4*)(Kt + ls * 64 + d0);
            uint4 kv1 = *(const uint4*)(Kt + ls * 64 + d0 + 8);
            const uint32_t* pk0 = (const uint32_t*)&kv0;
            const uint32_t* pk1 = (const uint32_t*)&kv1;
#pragma unroll
            for (int j = 0; j < 4; j++) {
                Ks[(dg8 + j) * 72 + ls]     = pk0[j];
                Ks[(dg8 + 4 + j) * 72 + ls] = pk1[j];
            }
            uint4 vv0 = *(const uint4*)(Vt + ls * 64 + d0);
            uint4 vv1 = *(const uint4*)(Vt + ls * 64 + d0 + 8);
            const __half* pv0 = (const __half*)&vv0;
            const __half* pv1 = (const __half*)&vv1;
#pragma unroll
            for (int j = 0; j < 8; j++) {
                Vs[(d0 + j) * 72 + ls]     = pv0[j];
                Vs[(d0 + 8 + j) * 72 + ls] = pv1[j];
            }
        }
        __syncthreads();

        // ---- S = Q K^T (fp16 m16n8k16): 4 k-steps x 8 key blocks ----
        float accs[8][4];
#pragma unroll
        for (int j = 0; j < 8; j++)
#pragma unroll
            for (int e = 0; e < 4; e++) accs[j][e] = 0.f;

        const int mrow = wid * 16 + g;
#pragma unroll
        for (int ks2 = 0; ks2 < 32; ks2 += 8) {
            uint32_t a0 = Qs[(ks2 + t) * 136 + mrow];
            uint32_t a1 = Qs[(ks2 + t) * 136 + mrow + 8];
            uint32_t a2 = Qs[(ks2 + 4 + t) * 136 + mrow];
            uint32_t a3 = Qs[(ks2 + 4 + t) * 136 + mrow + 8];
#pragma unroll
            for (int j = 0; j < 8; j++) {
                uint32_t b0 = Ks[(ks2 + t) * 72 + 8 * j + g];
                uint32_t b1 = Ks[(ks2 + 4 + t) * 72 + 8 * j + g];
                mma_f16(accs[j], a0, a1, a2, a3, b0, b1);
            }
        }

        // ---- online softmax (rows g, g+8 of warp slice) ----
        float mx0 = -1e30f, mx1 = -1e30f;
#pragma unroll
        for (int j = 0; j < 8; j++) {
            mx0 = fmaxf(mx0, fmaxf(accs[j][0], accs[j][1]));
            mx1 = fmaxf(mx1, fmaxf(accs[j][2], accs[j][3]));
        }
        mx0 = fmaxf(mx0, __shfl_xor_sync(0xffffffffu, mx0, 1));
        mx0 = fmaxf(mx0, __shfl_xor_sync(0xffffffffu, mx0, 2));
        mx1 = fmaxf(mx1, __shfl_xor_sync(0xffffffffu, mx1, 1));
        mx1 = fmaxf(mx1, __shfl_xor_sync(0xffffffffu, mx1, 2));

        const float mn0 = fmaxf(m0, mx0);
        const float mn1 = fmaxf(m1, mx1);
        const float c0 = ex2(m0 - mn0);
        const float c1 = ex2(m1 - mn1);

        float s0 = 0.f, s1 = 0.f;
#pragma unroll
        for (int j = 0; j < 8; j++) {
            accs[j][0] = ex2(accs[j][0] - mn0); s0 += accs[j][0];
            accs[j][1] = ex2(accs[j][1] - mn0); s0 += accs[j][1];
            accs[j][2] = ex2(accs[j][2] - mn1); s1 += accs[j][2];
            accs[j][3] = ex2(accs[j][3] - mn1); s1 += accs[j][3];
        }
        s0 += __shfl_xor_sync(0xffffffffu, s0, 1);
        s0 += __shfl_xor_sync(0xffffffffu, s0, 2);
        s1 += __shfl_xor_sync(0xffffffffu, s1, 1);
        s1 += __shfl_xor_sync(0xffffffffu, s1, 2);

        l0 = l0 * c0 + s0;
        l1 = l1 * c1 + s1;
        m0 = mn0;
        m1 = mn1;

#pragma unroll
        for (int d = 0; d < 8; d++) {
            accO[d][0] *= c0; accO[d][1] *= c0;
            accO[d][2] *= c1; accO[d][3] *= c1;
        }

        // ---- O += P V (fp16, P stays in registers) ----
#pragma unroll
        for (int kb = 0; kb < 4; kb++) {
            __half2 h0 = __float22half2_rn(make_float2(accs[2*kb][0],   accs[2*kb][1]));
            __half2 h1 = __float22half2_rn(make_float2(accs[2*kb][2],   accs[2*kb][3]));
            __half2 h2 = __float22half2_rn(make_float2(accs[2*kb+1][0], accs[2*kb+1][1]));
            __half2 h3 = __float22half2_rn(make_float2(accs[2*kb+1][2], accs[2*kb+1][3]));
            uint32_t pa0 = *(uint32_t*)&h0;
            uint32_t pa1 = *(uint32_t*)&h1;
            uint32_t pa2 = *(uint32_t*)&h2;
            uint32_t pa3 = *(uint32_t*)&h3;
#pragma unroll
            for (int db = 0; db < 8; db++) {
                const int drow = (8 * db + g) * 72 + 16 * kb + 2 * t;
                uint32_t b0 = *(const uint32_t*)&Vs[drow];
                uint32_t b1 = *(const uint32_t*)&Vs[drow + 8];
                mma_f16(accO[db], pa0, pa1, pa2, pa3, b0, b1);
            }
        }
    }

    // ---- epilogue: normalize, write f32 [B,S,H*D] ----
    const int b = bh >> 4, h = bh & 15;
    const float inv0 = 1.f / l0;
    const float inv1 = 1.f / l1;
    const int row0 = q0 + wid * 16 + g;
    const int row1 = row0 + 8;
#pragma unroll
    for (int db = 0; db < 8; db++) {
        const int d = db * 8 + 2 * t;
        float2 v0 = make_float2(accO[db][0] * inv0, accO[db][1] * inv0);
        float2 v1 = make_float2(accO[db][2] * inv1, accO[db][3] * inv1);
        *(float2*)(out + (b * Ssq + row0) * Ww + h * Dd + d) = v0;
        *(float2*)(out + (b * Ssq + row1) * Ww + h * Dd + d) = v1;
    }
}

// ---------------------------------------------------------------------------
extern "C" void kernel_launch(void* const* d_in, const int* in_sizes, int n_in,
                              void* d_out, int out_size)
{
    const float* from_t = (const float*)d_in[0];
    const float* to_t   = (const float*)d_in[1];
    const float* Wq     = (const float*)d_in[2];
    const float* bq     = (const float*)d_in[3];
    const float* Wk     = (const float*)d_in[4];
    const float* bk     = (const float*)d_in[5];
    const float* Wv     = (const float*)d_in[6];
    const float* bv     = (const float*)d_in[7];
    float* out = (float*)d_out;

    cvt_all<<<CVT_GROUPS / 256, 256>>>(from_t, to_t, Wq, Wk, Wv);

    dim3 g1(Ww / 128, (Bb * Ssq) / 128, 3);
    qkv_gemm_h<<<g1, 256>>>(bq, bk, bv);

    constexpr int smem_attn = 35840;
    cudaFuncSetAttribute(attn_h,
                         cudaFuncAttributeMaxDynamicSharedMemorySize,
                         smem_attn);
    dim3 g2(Ssq / 128, Bb * Hh);
    attn_h<<<g2, 256, smem_attn>>>(out);
}

// round 6
// speedup vs baseline: 6.2417x; 1.4999x over previous
#include <cuda_runtime.h>
#include <cuda_fp16.h>
#include <cstdint>

// Problem constants
#define Bb  8
#define Ssq 1024
#define Hh  16
#define Dd  64
#define Ww  1024   // hidden = H*D

#define QSCALE 0.1803368801111204f   // log2(e) / 8

// fp16 copies of inputs (one-time convert pass)
__device__ __half g_fh[Bb * Ssq * Ww];        // from_tensor fp16
__device__ __half g_th[Bb * Ssq * Ww];        // to_tensor fp16
__device__ __half g_wh[3 * Ww * Ww];          // Wq|Wk|Wv fp16

// Q/K/V in [B,H,S,D] fp16 (Q pre-scaled by QSCALE)
__device__ __half g_qh[Bb * Hh * Ssq * Dd];
__device__ __half g_kh[Bb * Hh * Ssq * Dd];
__device__ __half g_vh[Bb * Hh * Ssq * Dd];

__device__ __forceinline__ float ex2(float x) {
    float y;
    asm("ex2.approx.f32 %0, %1;" : "=f"(y) : "f"(x));
    return y;
}

__device__ __forceinline__ uint32_t smem_u32(const void* p) {
    uint32_t a;
    asm("{ .reg .u64 t; cvta.to.shared.u64 t, %1; cvt.u32.u64 %0, t; }"
        : "=r"(a) : "l"(p));
    return a;
}

__device__ __forceinline__ void mma_f16(float d[4], uint32_t a0, uint32_t a1,
                                        uint32_t a2, uint32_t a3,
                                        uint32_t b0, uint32_t b1) {
    asm volatile(
        "mma.sync.aligned.m16n8k16.row.col.f32.f16.f16.f32 "
        "{%0,%1,%2,%3}, {%4,%5,%6,%7}, {%8,%9}, {%0,%1,%2,%3};"
        : "+f"(d[0]), "+f"(d[1]), "+f"(d[2]), "+f"(d[3])
        : "r"(a0), "r"(a1), "r"(a2), "r"(a3), "r"(b0), "r"(b1));
}

__device__ __forceinline__ void ldsm4(uint32_t& r0, uint32_t& r1, uint32_t& r2,
                                      uint32_t& r3, uint32_t addr) {
    asm volatile("ldmatrix.sync.aligned.m8n8.x4.shared.b16 {%0,%1,%2,%3}, [%4];"
                 : "=r"(r0), "=r"(r1), "=r"(r2), "=r"(r3) : "r"(addr));
}
__device__ __forceinline__ void ldsm4t(uint32_t& r0, uint32_t& r1, uint32_t& r2,
                                       uint32_t& r3, uint32_t addr) {
    asm volatile("ldmatrix.sync.aligned.m8n8.x4.trans.shared.b16 {%0,%1,%2,%3}, [%4];"
                 : "=r"(r0), "=r"(r1), "=r"(r2), "=r"(r3) : "r"(addr));
}

__device__ __forceinline__ void cp16(uint32_t saddr, const void* g) {
    asm volatile("cp.async.cg.shared.global [%0], [%1], 16;"
                 :: "r"(saddr), "l"(g));
}
#define CP_COMMIT() asm volatile("cp.async.commit_group;")
#define CP_WAIT(n)  asm volatile("cp.async.wait_group %0;" :: "n"(n))

// ===========================================================================
// One-time f32 -> fp16 convert of all inputs (unchanged).
// ===========================================================================
#define CVT_GROUPS 4980736
__global__ __launch_bounds__(256) void cvt_all(
    const float* __restrict__ from_t, const float* __restrict__ to_t,
    const float* __restrict__ Wq, const float* __restrict__ Wk,
    const float* __restrict__ Wv)
{
    long gidx = (long)blockIdx.x * 256 + threadIdx.x;
    const float* src;
    __half* dst;
    long off;
    if (gidx < 2097152)      { src = from_t; dst = g_fh; off = gidx; }
    else if (gidx < 4194304) { src = to_t;   dst = g_th; off = gidx - 2097152; }
    else if (gidx < 4456448) { src = Wq; dst = g_wh;               off = gidx - 4194304; }
    else if (gidx < 4718592) { src = Wk; dst = g_wh + Ww * Ww;     off = gidx - 4456448; }
    else                     { src = Wv; dst = g_wh + 2 * Ww * Ww; off = gidx - 4718592; }
    float4 v = *(const float4*)(src + off * 4);
    __half2 h0 = __float22half2_rn(make_float2(v.x, v.y));
    __half2 h1 = __float22half2_rn(make_float2(v.z, v.w));
    *(uint2*)(dst + off * 4) = make_uint2(*(uint32_t*)&h0, *(uint32_t*)&h1);
}

// ===========================================================================
// QKV projection, fp16 mma + cp.async + ldmatrix.
// CTA 128x128, 8 warps (2M x 4N), warp 64x32, K chunks of 32, double buffer.
// As[m][k] natural (stride 40), Bs[k][n] natural (stride 136).
// A frags: ldmatrix.x4; B frags: ldmatrix.x4.trans.
// ===========================================================================
#define NCH 32

__global__ __launch_bounds__(256) void qkv_gemm_h(
    const float* __restrict__ bq, const float* __restrict__ bk,
    const float* __restrict__ bv)
{
    __shared__ __align__(16) __half As[2][128][40];
    __shared__ __align__(16) __half Bs[2][32][136];

    const int which = blockIdx.z;
    const __half* A  = (which == 0) ? g_fh : g_th;
    const __half* Wm = g_wh + which * (Ww * Ww);
    const float* bbv = (which == 0) ? bq : (which == 1) ? bk : bv;
    __half* outp     = (which == 0) ? g_qh : (which == 1) ? g_kh : g_vh;
    const float sc   = (which == 0) ? QSCALE : 1.0f;

    const int tid = threadIdx.x;
    const int wid = tid >> 5;
    const int lane = tid & 31;
    const int m0 = blockIdx.y * 128;
    const int n0 = blockIdx.x * 128;

    const int wm = wid & 1;
    const int wn = wid >> 1;
    const int lq = lane >> 2;
    const int lr = lane & 3;

    const uint32_t sa0 = smem_u32(&As[0][0][0]);
    const uint32_t sb0 = smem_u32(&Bs[0][0][0]);

    // fragment base addresses (buf 0)
    const uint32_t a_frag = sa0 +
        (((wm * 64 + (lane & 15)) * 40) + 8 * (lane >> 4)) * 2;
    const uint32_t b_frag = sb0 +
        (((lane & 7) + 8 * ((lane >> 3) & 1)) * 136 + wn * 32 + 8 * (lane >> 4)) * 2;

    float acc[4][4][4];
#pragma unroll
    for (int mi = 0; mi < 4; mi++)
#pragma unroll
        for (int nj = 0; nj < 4; nj++)
#pragma unroll
            for (int e = 0; e < 4; e++) acc[mi][nj][e] = 0.f;

    auto issue = [&](int k0, int buf) {
#pragma unroll
        for (int j = 0; j < 2; j++) {
            const int idx = tid + j * 256;
            const int row = idx >> 2, kof = (idx & 3) * 8;
            cp16(sa0 + buf * 10240 + (row * 40 + kof) * 2,
                 A + (m0 + row) * Ww + k0 + kof);
            const int br = idx >> 4, bn = (idx & 15) * 8;
            cp16(sb0 + buf * 8704 + (br * 136 + bn) * 2,
                 Wm + (k0 + br) * Ww + n0 + bn);
        }
    };

    issue(0, 0);
    CP_COMMIT();

#pragma unroll 1
    for (int i = 0; i < NCH; i++) {
        const int b = i & 1;
        if (i + 1 < NCH) {
            issue((i + 1) * 32, b ^ 1);
            CP_COMMIT();
            CP_WAIT(1);
        } else {
            CP_WAIT(0);
        }
        __syncthreads();

#pragma unroll
        for (int ks = 0; ks < 2; ks++) {
            uint32_t bf[4][2];
#pragma unroll
            for (int pj = 0; pj < 2; pj++) {
                uint32_t r0, r1, r2, r3;
                ldsm4t(r0, r1, r2, r3,
                       b_frag + b * 8704 + ks * 4352 + pj * 32);
                bf[2 * pj][0] = r0;     bf[2 * pj][1] = r1;
                bf[2 * pj + 1][0] = r2; bf[2 * pj + 1][1] = r3;
            }
#pragma unroll
            for (int mi = 0; mi < 4; mi++) {
                uint32_t a0, a1, a2, a3;
                ldsm4(a0, a1, a2, a3,
                      a_frag + b * 10240 + mi * 1280 + ks * 32);
#pragma unroll
                for (int nj = 0; nj < 4; nj++)
                    mma_f16(acc[mi][nj], a0, a1, a2, a3, bf[nj][0], bf[nj][1]);
            }
        }
        __syncthreads();
    }

    // epilogue: bias (+scale for Q), fp16 scatter to [B,H,S,D]
#pragma unroll
    for (int mi = 0; mi < 4; mi++) {
        const int mA = m0 + wm * 64 + mi * 16 + lq;
        const int mB = mA + 8;
        const int biA = mA >> 10, sA = mA & 1023;
        const int biB = mB >> 10, sB = mB & 1023;
#pragma unroll
        for (int nj = 0; nj < 4; nj++) {
            const int n = n0 + wn * 32 + nj * 8 + 2 * lr;
            const int h = n >> 6, d = n & 63;
            const float bx = __ldg(bbv + n), by = __ldg(bbv + n + 1);
            __half2 v0 = __float22half2_rn(make_float2(
                (acc[mi][nj][0] + bx) * sc, (acc[mi][nj][1] + by) * sc));
            __half2 v1 = __float22half2_rn(make_float2(
                (acc[mi][nj][2] + bx) * sc, (acc[mi][nj][3] + by) * sc));
            *(__half2*)(outp + ((biA * Hh + h) * Ssq + sA) * Dd + d) = v0;
            *(__half2*)(outp + ((biB * Hh + h) * Ssq + sB) * Dd + d) = v1;
        }
    }
}

// ===========================================================================
// Flash attention, fp16 mma + cp.async double-buffered K/V + ldmatrix.
// Br=128 (8 warps x 16 rows), Bc=64, 16 K-tiles. Q frags hoisted.
// All tiles natural [row][d] layout, stride 72 halfs:
//   Q -> A frag: ldmatrix.x4        K -> B frag (QK^T): ldmatrix.x4
//   V -> B frag (PV): ldmatrix.x4.trans
// smem: Qs[128][72] | Ks[2][64][72] | Vs[2][64][72] = 55296 B dynamic.
// ===========================================================================
__global__ __launch_bounds__(256) void attn_h(float* __restrict__ out)
{
    extern __shared__ char smraw[];
    const uint32_t sq = smem_u32(smraw);
    const uint32_t sk = sq + 18432;
    const uint32_t sv = sk + 18432;      // sk + buf*9216 ; sv + buf*9216

    const int tid = threadIdx.x;
    const int wid = tid >> 5;
    const int lane = tid & 31;
    const int g = lane >> 2;
    const int t = lane & 3;

    const int bh = blockIdx.y;
    const int q0 = blockIdx.x * 128;

    const __half* Qg = g_qh + (bh * Ssq + q0) * Dd;
    const __half* Kg = g_kh + bh * Ssq * Dd;
    const __half* Vg = g_vh + bh * Ssq * Dd;

    // prologue: Q tile + K/V tile 0 via cp.async
#pragma unroll
    for (int j = 0; j < 4; j++) {
        const int idx = tid + j * 256;
        const int row = idx >> 3, dof = (idx & 7) * 8;
        cp16(sq + (row * 72 + dof) * 2, Qg + row * 64 + dof);
    }
#pragma unroll
    for (int j = 0; j < 2; j++) {
        const int idx = tid + j * 256;
        const int row = idx >> 3, dof = (idx & 7) * 8;
        cp16(sk + (row * 72 + dof) * 2, Kg + row * 64 + dof);
        cp16(sv + (row * 72 + dof) * 2, Vg + row * 64 + dof);
    }
    CP_COMMIT();
    CP_WAIT(0);
    __syncthreads();

    // hoisted Q fragments (loop-invariant)
    uint32_t aq[4][4];
    const uint32_t q_frag = sq +
        ((wid * 16 + (lane & 15)) * 72 + 8 * (lane >> 4)) * 2;
#pragma unroll
    for (int ks = 0; ks < 4; ks++)
        ldsm4(aq[ks][0], aq[ks][1], aq[ks][2], aq[ks][3], q_frag + ks * 32);

    // fragment base addresses (buf 0)
    const uint32_t k_frag = sk +
        ((8 * (lane >> 4) + (lane & 7)) * 72 + 8 * ((lane >> 3) & 1)) * 2;
    const uint32_t v_frag = sv +
        ((8 * ((lane >> 3) & 1) + (lane & 7)) * 72 + 8 * (lane >> 4)) * 2;

    float m0 = -1e30f, m1 = -1e30f, l0 = 0.f, l1 = 0.f;
    float accO[8][4];
#pragma unroll
    for (int d = 0; d < 8; d++)
#pragma unroll
        for (int e = 0; e < 4; e++) accO[d][e] = 0.f;

#pragma unroll 1
    for (int kt = 0; kt < 16; kt++) {
        const int b = kt & 1;
        if (kt < 15) {
            const __half* Kt = Kg + (kt + 1) * 4096;
            const __half* Vt = Vg + (kt + 1) * 4096;
            const uint32_t nb = (b ^ 1) * 9216;
#pragma unroll
            for (int j = 0; j < 2; j++) {
                const int idx = tid + j * 256;
                const int row = idx >> 3, dof = (idx & 7) * 8;
                cp16(sk + nb + (row * 72 + dof) * 2, Kt + row * 64 + dof);
                cp16(sv + nb + (row * 72 + dof) * 2, Vt + row * 64 + dof);
            }
            CP_COMMIT();
            CP_WAIT(1);
        } else {
            CP_WAIT(0);
        }
        __syncthreads();

        // ---- S = Q K^T ----
        float accs[8][4];
#pragma unroll
        for (int j = 0; j < 8; j++)
#pragma unroll
            for (int e = 0; e < 4; e++) accs[j][e] = 0.f;

#pragma unroll
        for (int ks = 0; ks < 4; ks++) {
#pragma unroll
            for (int jj = 0; jj < 4; jj++) {
                uint32_t r0, r1, r2, r3;
                ldsm4(r0, r1, r2, r3,
                      k_frag + b * 9216 + jj * 2304 + ks * 32);
                mma_f16(accs[2 * jj],     aq[ks][0], aq[ks][1], aq[ks][2],
                        aq[ks][3], r0, r1);
                mma_f16(accs[2 * jj + 1], aq[ks][0], aq[ks][1], aq[ks][2],
                        aq[ks][3], r2, r3);
            }
        }

        // ---- online softmax (rows g, g+8 of warp slice) ----
        float mx0 = -1e30f, mx1 = -1e30f;
#pragma unroll
        for (int j = 0; j < 8; j++) {
            mx0 = fmaxf(mx0, fmaxf(accs[j][0], accs[j][1]));
            mx1 = fmaxf(mx1, fmaxf(accs[j][2], accs[j][3]));
        }
        mx0 = fmaxf(mx0, __shfl_xor_sync(0xffffffffu, mx0, 1));
        mx0 = fmaxf(mx0, __shfl_xor_sync(0xffffffffu, mx0, 2));
        mx1 = fmaxf(mx1, __shfl_xor_sync(0xffffffffu, mx1, 1));
        mx1 = fmaxf(mx1, __shfl_xor_sync(0xffffffffu, mx1, 2));

        const float mn0 = fmaxf(m0, mx0);
        const float mn1 = fmaxf(m1, mx1);
        const float c0 = ex2(m0 - mn0);
        const float c1 = ex2(m1 - mn1);

        float s0 = 0.f, s1 = 0.f;
#pragma unroll
        for (int j = 0; j < 8; j++) {
            accs[j][0] = ex2(accs[j][0] - mn0); s0 += accs[j][0];
            accs[j][1] = ex2(accs[j][1] - mn0); s0 += accs[j][1];
            accs[j][2] = ex2(accs[j][2] - mn1); s1 += accs[j][2];
            accs[j][3] = ex2(accs[j][3] - mn1); s1 += accs[j][3];
        }
        s0 += __shfl_xor_sync(0xffffffffu, s0, 1);
        s0 += __shfl_xor_sync(0xffffffffu, s0, 2);
        s1 += __shfl_xor_sync(0xffffffffu, s1, 1);
        s1 += __shfl_xor_sync(0xffffffffu, s1, 2);

        l0 = l0 * c0 + s0;
        l1 = l1 * c1 + s1;
        m0 = mn0;
        m1 = mn1;

#pragma unroll
        for (int d = 0; d < 8; d++) {
            accO[d][0] *= c0; accO[d][1] *= c0;
            accO[d][2] *= c1; accO[d][3] *= c1;
        }

        // ---- O += P V ----
#pragma unroll
        for (int kb = 0; kb < 4; kb++) {
            __half2 h0 = __float22half2_rn(make_float2(accs[2*kb][0],   accs[2*kb][1]));
            __half2 h1 = __float22half2_rn(make_float2(accs[2*kb][2],   accs[2*kb][3]));
            __half2 h2 = __float22half2_rn(make_float2(accs[2*kb+1][0], accs[2*kb+1][1]));
            __half2 h3 = __float22half2_rn(make_float2(accs[2*kb+1][2], accs[2*kb+1][3]));
            const uint32_t pa0 = *(uint32_t*)&h0;
            const uint32_t pa1 = *(uint32_t*)&h1;
            const uint32_t pa2 = *(uint32_t*)&h2;
            const uint32_t pa3 = *(uint32_t*)&h3;
#pragma unroll
            for (int dd = 0; dd < 4; dd++) {
                uint32_t r0, r1, r2, r3;
                ldsm4t(r0, r1, r2, r3,
                       v_frag + b * 9216 + kb * 2304 + dd * 32);
                mma_f16(accO[2 * dd],     pa0, pa1, pa2, pa3, r0, r1);
                mma_f16(accO[2 * dd + 1], pa0, pa1, pa2, pa3, r2, r3);
            }
        }
        __syncthreads();
    }

    // ---- epilogue: normalize, write f32 [B,S,H*D] ----
    const int b = bh >> 4, h = bh & 15;
    const float inv0 = 1.f / l0;
    const float inv1 = 1.f / l1;
    const int row0 = q0 + wid * 16 + g;
    const int row1 = row0 + 8;
#pragma unroll
    for (int db = 0; db < 8; db++) {
        const int d = db * 8 + 2 * t;
        float2 v0 = make_float2(accO[db][0] * inv0, accO[db][1] * inv0);
        float2 v1 = make_float2(accO[db][2] * inv1, accO[db][3] * inv1);
        *(float2*)(out + (b * Ssq + row0) * Ww + h * Dd + d) = v0;
        *(float2*)(out + (b * Ssq + row1) * Ww + h * Dd + d) = v1;
    }
}

// ---------------------------------------------------------------------------
extern "C" void kernel_launch(void* const* d_in, const int* in_sizes, int n_in,
                              void* d_out, int out_size)
{
    const float* from_t = (const float*)d_in[0];
    const float* to_t   = (const float*)d_in[1];
    const float* Wq     = (const float*)d_in[2];
    const float* bq     = (const float*)d_in[3];
    const float* Wk     = (const float*)d_in[4];
    const float* bk     = (const float*)d_in[5];
    const float* Wv     = (const float*)d_in[6];
    const float* bv     = (const float*)d_in[7];
    float* out = (float*)d_out;

    cvt_all<<<CVT_GROUPS / 256, 256>>>(from_t, to_t, Wq, Wk, Wv);

    dim3 g1(Ww / 128, (Bb * Ssq) / 128, 3);
    qkv_gemm_h<<<g1, 256>>>(bq, bk, bv);

    constexpr int smem_attn = 55296;
    cudaFuncSetAttribute(attn_h,
                         cudaFuncAttributeMaxDynamicSharedMemorySize,
                         smem_attn);
    dim3 g2(Ssq / 128, Bb * Hh);
    attn_h<<<g2, 256, smem_attn>>>(out);
}